// round 11
// baseline (speedup 1.0000x reference)
#include <cuda_runtime.h>
#include <math.h>

// ---------------- problem constants ----------------
#define EMBED    1024
#define HEADS    16
#define HEAD_DIM 64
#define FFDIM    4096
#define LAYERS   4
#define BATCH    2
#define SEQ      2048
#define ROWS     (BATCH * SEQ)   // 4096
#define BANDW    46              // ceil(sqrt(2048))

// attention tiling
#define QT    64
#define KT    (QT + 2 * BANDW)   // 156
#define PITCH 68                 // padded row pitch (floats) for Q/K/V smem

// ---------------- scratch (device globals; no allocation allowed) ----------------
__device__ float g_q[ROWS * EMBED];
__device__ float g_k[ROWS * EMBED];
__device__ float g_v[ROWS * EMBED];
__device__ float g_attn[ROWS * EMBED];
__device__ float g_proj[ROWS * EMBED];
__device__ float g_x[ROWS * EMBED];
__device__ float g_x2[ROWS * EMBED];
__device__ float g_ffbuf[ROWS * FFDIM];

// ---------------- SGEMM: C[M,N] = A[M,K] @ W[N,K]^T + bias, optional ReLU ----------------
// 128x128 tile, BK=8, 256 threads, 8x8 per thread, fp32.
__global__ __launch_bounds__(256) void sgemm_nt(
    const float* __restrict__ A, const float* __restrict__ W,
    const float* __restrict__ bias, float* __restrict__ C,
    int M, int N, int K, int relu)
{
    __shared__ float As[8][128];
    __shared__ float Bs[8][128];
    const int tid = threadIdx.x;
    const int m0 = blockIdx.y * 128;
    const int n0 = blockIdx.x * 128;
    const int lrow = tid >> 1;
    const int lcol = (tid & 1) * 4;
    const float* Ap = A + (size_t)(m0 + lrow) * K + lcol;
    const float* Wp = W + (size_t)(n0 + lrow) * K + lcol;
    const int tx = tid & 15;
    const int ty = tid >> 4;

    float acc[8][8];
#pragma unroll
    for (int i = 0; i < 8; i++)
#pragma unroll
        for (int j = 0; j < 8; j++) acc[i][j] = 0.f;

    float4 a = *(const float4*)(Ap);
    float4 b = *(const float4*)(Wp);
    for (int k0 = 0; k0 < K; k0 += 8) {
        As[lcol + 0][lrow] = a.x;
        As[lcol + 1][lrow] = a.y;
        As[lcol + 2][lrow] = a.z;
        As[lcol + 3][lrow] = a.w;
        Bs[lcol + 0][lrow] = b.x;
        Bs[lcol + 1][lrow] = b.y;
        Bs[lcol + 2][lrow] = b.z;
        Bs[lcol + 3][lrow] = b.w;
        __syncthreads();
        if (k0 + 8 < K) {
            a = *(const float4*)(Ap + k0 + 8);
            b = *(const float4*)(Wp + k0 + 8);
        }
#pragma unroll
        for (int kk = 0; kk < 8; kk++) {
            float ar[8], br[8];
            *(float4*)(ar)     = *(const float4*)(&As[kk][ty * 4]);
            *(float4*)(ar + 4) = *(const float4*)(&As[kk][64 + ty * 4]);
            *(float4*)(br)     = *(const float4*)(&Bs[kk][tx * 4]);
            *(float4*)(br + 4) = *(const float4*)(&Bs[kk][64 + tx * 4]);
#pragma unroll
            for (int i = 0; i < 8; i++)
#pragma unroll
                for (int j = 0; j < 8; j++)
                    acc[i][j] += ar[i] * br[j];
        }
        __syncthreads();
    }

    float4 bias0 = *(const float4*)(bias + n0 + tx * 4);
    float4 bias1 = *(const float4*)(bias + n0 + 64 + tx * 4);
#pragma unroll
    for (int i = 0; i < 8; i++) {
        int row = m0 + ((i < 4) ? (ty * 4 + i) : (64 + ty * 4 + (i - 4)));
        float4 r0, r1;
        r0.x = acc[i][0] + bias0.x;
        r0.y = acc[i][1] + bias0.y;
        r0.z = acc[i][2] + bias0.z;
        r0.w = acc[i][3] + bias0.w;
        r1.x = acc[i][4] + bias1.x;
        r1.y = acc[i][5] + bias1.y;
        r1.z = acc[i][6] + bias1.z;
        r1.w = acc[i][7] + bias1.w;
        if (relu) {
            r0.x = fmaxf(r0.x, 0.f); r0.y = fmaxf(r0.y, 0.f);
            r0.z = fmaxf(r0.z, 0.f); r0.w = fmaxf(r0.w, 0.f);
            r1.x = fmaxf(r1.x, 0.f); r1.y = fmaxf(r1.y, 0.f);
            r1.z = fmaxf(r1.z, 0.f); r1.w = fmaxf(r1.w, 0.f);
        }
        *(float4*)(C + (size_t)row * N + n0 + tx * 4)      = r0;
        *(float4*)(C + (size_t)row * N + n0 + 64 + tx * 4) = r1;
    }
}

// ---------------- banded attention ----------------
// One CTA per (batch, head, 64-query tile). Keys/values windowed to 156 rows.
// Layout of q/k/v/o buffers: [B, S, H*D] with head h occupying cols h*64..h*64+63.
#define ATTN_SMEM_FLOATS (QT * PITCH + 2 * KT * PITCH + QT * KT)
#define ATTN_SMEM_BYTES  (ATTN_SMEM_FLOATS * 4)

__global__ __launch_bounds__(256) void band_attn(
    const float* __restrict__ q, const float* __restrict__ k,
    const float* __restrict__ v, float* __restrict__ o)
{
    extern __shared__ float sm[];
    float* Qs = sm;                       // QT * PITCH
    float* Ks = Qs + QT * PITCH;          // KT * PITCH
    float* Vs = Ks + KT * PITCH;          // KT * PITCH
    float* Ss = Vs + KT * PITCH;          // QT * KT

    const int t  = threadIdx.x;           // 256
    const int q0 = blockIdx.x * QT;
    const int h  = blockIdx.y;
    const int b  = blockIdx.z;
    const size_t hoff = (size_t)h * HEAD_DIM;

    // load Q tile
    for (int idx = t; idx < QT * 16; idx += 256) {
        int i  = idx >> 4;
        int d4 = (idx & 15) * 4;
        float4 val = *(const float4*)(q + ((size_t)(b * SEQ + q0 + i) * EMBED) + hoff + d4);
        Qs[i * PITCH + d4 + 0] = val.x;
        Qs[i * PITCH + d4 + 1] = val.y;
        Qs[i * PITCH + d4 + 2] = val.z;
        Qs[i * PITCH + d4 + 3] = val.w;
    }
    // load K/V window (zero-fill outside sequence)
    for (int idx = t; idx < KT * 16; idx += 256) {
        int jj = idx >> 4;
        int d4 = (idx & 15) * 4;
        int j  = q0 - BANDW + jj;
        float4 kv = make_float4(0.f, 0.f, 0.f, 0.f);
        float4 vv = make_float4(0.f, 0.f, 0.f, 0.f);
        if (j >= 0 && j < SEQ) {
            size_t base = ((size_t)(b * SEQ + j) * EMBED) + hoff + d4;
            kv = *(const float4*)(k + base);
            vv = *(const float4*)(v + base);
        }
        Ks[jj * PITCH + d4 + 0] = kv.x;
        Ks[jj * PITCH + d4 + 1] = kv.y;
        Ks[jj * PITCH + d4 + 2] = kv.z;
        Ks[jj * PITCH + d4 + 3] = kv.w;
        Vs[jj * PITCH + d4 + 0] = vv.x;
        Vs[jj * PITCH + d4 + 1] = vv.y;
        Vs[jj * PITCH + d4 + 2] = vv.z;
        Vs[jj * PITCH + d4 + 3] = vv.w;
    }
    __syncthreads();

    // scores
    const float scale = 0.125f;  // 1/sqrt(64)
    const int i  = t >> 2;
    const int jl = t & 3;
    for (int jj = jl; jj < KT; jj += 4) {
        int j = q0 - BANDW + jj;
        float sres = -1e9f;
        if (jj >= i && jj <= i + 2 * BANDW && j >= 0 && j < SEQ) {
            const float4* qp = (const float4*)(Qs + i * PITCH);
            const float4* kp = (const float4*)(Ks + jj * PITCH);
            float accv = 0.f;
#pragma unroll
            for (int d4 = 0; d4 < 16; d4++) {
                float4 aa = qp[d4], cc = kp[d4];
                accv += aa.x * cc.x + aa.y * cc.y + aa.z * cc.z + aa.w * cc.w;
            }
            sres = accv * scale;
        }
        Ss[i * KT + jj] = sres;
    }
    __syncthreads();

    // softmax (one thread per query row)
    if (t < QT) {
        float* srow = Ss + t * KT;
        float mx = -1e30f;
        for (int jj = 0; jj < KT; jj++) mx = fmaxf(mx, srow[jj]);
        float sum = 0.f;
        for (int jj = 0; jj < KT; jj++) {
            float e = expf(srow[jj] - mx);
            srow[jj] = e;
            sum += e;
        }
        float inv = 1.f / sum;
        for (int jj = 0; jj < KT; jj++) srow[jj] *= inv;
    }
    __syncthreads();

    // output: thread handles (i, 16 contiguous dims)
    const int dblk = (t & 3) * 16;
    float acc[16];
#pragma unroll
    for (int kk = 0; kk < 16; kk++) acc[kk] = 0.f;
    for (int jj = 0; jj < KT; jj++) {
        float p = Ss[i * KT + jj];
        const float4* vp = (const float4*)(Vs + jj * PITCH + dblk);
#pragma unroll
        for (int k4 = 0; k4 < 4; k4++) {
            float4 vv = vp[k4];
            acc[k4 * 4 + 0] += p * vv.x;
            acc[k4 * 4 + 1] += p * vv.y;
            acc[k4 * 4 + 2] += p * vv.z;
            acc[k4 * 4 + 3] += p * vv.w;
        }
    }
    float* op = o + ((size_t)(b * SEQ + q0 + i) * EMBED) + hoff + dblk;
#pragma unroll
    for (int k4 = 0; k4 < 4; k4++) {
        float4 r;
        r.x = acc[k4 * 4 + 0];
        r.y = acc[k4 * 4 + 1];
        r.z = acc[k4 * 4 + 2];
        r.w = acc[k4 * 4 + 3];
        *(float4*)(op + k4 * 4) = r;
    }
}

// ---------------- fused residual add + LayerNorm ----------------
// y = LN(r + p) * g + be ; one block per row of 1024, 256 threads, float4 each.
__global__ __launch_bounds__(256) void add_ln(
    const float* __restrict__ r, const float* __restrict__ p,
    const float* __restrict__ g, const float* __restrict__ be,
    float* __restrict__ y)
{
    const int row = blockIdx.x;
    const int t = threadIdx.x;
    const size_t base = (size_t)row * EMBED + t * 4;
    float4 rv = *(const float4*)(r + base);
    float4 pv = *(const float4*)(p + base);
    float z0 = rv.x + pv.x, z1 = rv.y + pv.y, z2 = rv.z + pv.z, z3 = rv.w + pv.w;
    float s  = z0 + z1 + z2 + z3;
    float sq = z0 * z0 + z1 * z1 + z2 * z2 + z3 * z3;
#pragma unroll
    for (int off = 16; off > 0; off >>= 1) {
        s  += __shfl_xor_sync(0xffffffffu, s, off);
        sq += __shfl_xor_sync(0xffffffffu, sq, off);
    }
    __shared__ float ws[8], wsq[8];
    __shared__ float mu_s, rstd_s;
    const int warp = t >> 5, lane = t & 31;
    if (lane == 0) { ws[warp] = s; wsq[warp] = sq; }
    __syncthreads();
    if (t == 0) {
        float ts = 0.f, tsq = 0.f;
#pragma unroll
        for (int wdx = 0; wdx < 8; wdx++) { ts += ws[wdx]; tsq += wsq[wdx]; }
        float mu = ts * (1.f / EMBED);
        float var = tsq * (1.f / EMBED) - mu * mu;
        mu_s = mu;
        rstd_s = rsqrtf(var + 1e-5f);
    }
    __syncthreads();
    float mu = mu_s, rstd = rstd_s;
    float4 gv = *(const float4*)(g + t * 4);
    float4 bv = *(const float4*)(be + t * 4);
    float4 out;
    out.x = (z0 - mu) * rstd * gv.x + bv.x;
    out.y = (z1 - mu) * rstd * gv.y + bv.y;
    out.z = (z2 - mu) * rstd * gv.z + bv.z;
    out.w = (z3 - mu) * rstd * gv.w + bv.w;
    *(float4*)(y + base) = out;
}

// ---------------- launch ----------------
extern "C" void kernel_launch(void* const* d_in, const int* in_sizes, int n_in,
                              void* d_out, int out_size)
{
    static bool inited = false;
    static float *pq, *pk, *pv, *pattn, *pproj, *px, *px2, *pff;
    if (!inited) {
        cudaGetSymbolAddress((void**)&pq,    g_q);
        cudaGetSymbolAddress((void**)&pk,    g_k);
        cudaGetSymbolAddress((void**)&pv,    g_v);
        cudaGetSymbolAddress((void**)&pattn, g_attn);
        cudaGetSymbolAddress((void**)&pproj, g_proj);
        cudaGetSymbolAddress((void**)&px,    g_x);
        cudaGetSymbolAddress((void**)&px2,   g_x2);
        cudaGetSymbolAddress((void**)&pff,   g_ffbuf);
        cudaFuncSetAttribute(band_attn, cudaFuncAttributeMaxDynamicSharedMemorySize,
                             ATTN_SMEM_BYTES);
        inited = true;
    }

    const float* x   = (const float*)d_in[0];
    const float* Wq  = (const float*)d_in[1];
    const float* bq  = (const float*)d_in[2];
    const float* Wk  = (const float*)d_in[3];
    const float* bk  = (const float*)d_in[4];
    const float* Wv  = (const float*)d_in[5];
    const float* bv  = (const float*)d_in[6];
    const float* Wo  = (const float*)d_in[7];
    const float* bo  = (const float*)d_in[8];
    const float* W1  = (const float*)d_in[9];
    const float* b1  = (const float*)d_in[10];
    const float* W2  = (const float*)d_in[11];
    const float* b2  = (const float*)d_in[12];
    const float* g1  = (const float*)d_in[13];
    const float* be1 = (const float*)d_in[14];
    const float* g2  = (const float*)d_in[15];
    const float* be2 = (const float*)d_in[16];
    float* out = (float*)d_out;

    const dim3 gE(EMBED / 128, ROWS / 128);   // (8, 32)
    const dim3 gF(FFDIM / 128, ROWS / 128);   // (32, 32)
    const dim3 gA(SEQ / QT, HEADS, BATCH);    // (32, 16, 2)

    const float* cur = x;
    for (int L = 0; L < LAYERS; L++) {
        const size_t oEE = (size_t)L * EMBED * EMBED;
        const size_t oE  = (size_t)L * EMBED;
        const size_t oFE = (size_t)L * FFDIM * EMBED;
        const size_t oF  = (size_t)L * FFDIM;

        sgemm_nt<<<gE, 256>>>(cur, Wq + oEE, bq + oE, pq, ROWS, EMBED, EMBED, 0);
        sgemm_nt<<<gE, 256>>>(cur, Wk + oEE, bk + oE, pk, ROWS, EMBED, EMBED, 0);
        sgemm_nt<<<gE, 256>>>(cur, Wv + oEE, bv + oE, pv, ROWS, EMBED, EMBED, 0);

        band_attn<<<gA, 256, ATTN_SMEM_BYTES>>>(pq, pk, pv, pattn);

        sgemm_nt<<<gE, 256>>>(pattn, Wo + oEE, bo + oE, pproj, ROWS, EMBED, EMBED, 0);
        add_ln<<<ROWS, 256>>>(cur, pproj, g1 + oE, be1 + oE, px2);

        sgemm_nt<<<gF, 256>>>(px2, W1 + oFE, b1 + oF, pff, ROWS, FFDIM, EMBED, 1);
        sgemm_nt<<<gE, 256>>>(pff, W2 + oFE, b2 + oE, pproj, ROWS, EMBED, FFDIM, 0);

        float* dst = (L == LAYERS - 1) ? out : px;
        add_ln<<<ROWS, 256>>>(px2, pproj, g2 + oE, be2 + oE, dst);
        cur = px;
    }
}

// round 14
// speedup vs baseline: 2.1471x; 2.1471x over previous
#include <cuda_runtime.h>
#include <cuda_bf16.h>
#include <math.h>
#include <stdint.h>

// ---------------- problem constants ----------------
#define EMBED    1024
#define HEADS    16
#define HEAD_DIM 64
#define FFDIM    4096
#define LAYERS   4
#define BATCH    2
#define SEQ      2048
#define ROWS     (BATCH * SEQ)   // 4096
#define BANDW    46              // ceil(sqrt(2048))

// attention tiling
#define QT    64
#define KT    (QT + 2 * BANDW)   // 156
#define PITCH 68

// ---------------- scratch (device globals; no allocation allowed) ----------------
__device__ __align__(256) float g_q[ROWS * EMBED];
__device__ __align__(256) float g_k[ROWS * EMBED];
__device__ __align__(256) float g_v[ROWS * EMBED];
__device__ __align__(256) float g_attn[ROWS * EMBED];
__device__ __align__(256) float g_proj[ROWS * EMBED];
__device__ __align__(256) float g_x[ROWS * EMBED];
__device__ __align__(256) float g_x2[ROWS * EMBED];
__device__ __align__(256) float g_ffbuf[ROWS * FFDIM];

// split-precision bf16 operand buffers
__device__ __align__(256) __nv_bfloat16 g_ah[ROWS * EMBED];
__device__ __align__(256) __nv_bfloat16 g_al[ROWS * EMBED];
__device__ __align__(256) __nv_bfloat16 g_fh[ROWS * FFDIM];
__device__ __align__(256) __nv_bfloat16 g_fl[ROWS * FFDIM];
__device__ __align__(256) __nv_bfloat16 g_wh[FFDIM * EMBED];
__device__ __align__(256) __nv_bfloat16 g_wl[FFDIM * EMBED];

// ================= helpers =================
__device__ __forceinline__ uint32_t smem_u32(const void* p) {
    uint32_t a;
    asm("{ .reg .u64 t; cvta.to.shared.u64 t, %1; cvt.u32.u64 %0, t; }"
        : "=r"(a) : "l"(p));
    return a;
}

__device__ __forceinline__ void ldsm4(uint32_t r[4], uint32_t addr) {
    asm volatile("ldmatrix.sync.aligned.m8n8.x4.shared.b16 {%0,%1,%2,%3}, [%4];"
                 : "=r"(r[0]), "=r"(r[1]), "=r"(r[2]), "=r"(r[3]) : "r"(addr));
}

__device__ __forceinline__ void mma16816(float c[4], const uint32_t a[4],
                                         uint32_t b0, uint32_t b1) {
    asm volatile(
        "mma.sync.aligned.m16n8k16.row.col.f32.bf16.bf16.f32 "
        "{%0,%1,%2,%3}, {%4,%5,%6,%7}, {%8,%9}, {%0,%1,%2,%3};"
        : "+f"(c[0]), "+f"(c[1]), "+f"(c[2]), "+f"(c[3])
        : "r"(a[0]), "r"(a[1]), "r"(a[2]), "r"(a[3]), "r"(b0), "r"(b1));
}

#define CP_ASYNC16(dst, src) \
    asm volatile("cp.async.cg.shared.global [%0], [%1], 16;" :: "r"(dst), "l"(src))
#define CP_COMMIT() asm volatile("cp.async.commit_group;" ::: "memory")
#define CP_WAIT1()  asm volatile("cp.async.wait_group 1;" ::: "memory")

// ================= split conversion: fp32 -> (bf16 hi, bf16 lo) =================
__global__ __launch_bounds__(256) void convert_split(
    const float* __restrict__ in, __nv_bfloat16* __restrict__ hi,
    __nv_bfloat16* __restrict__ lo, int n)
{
    int i = (blockIdx.x * 256 + threadIdx.x) * 8;
    if (i >= n) return;
    float4 a = *(const float4*)(in + i);
    float4 b = *(const float4*)(in + i + 4);
    float v[8] = {a.x, a.y, a.z, a.w, b.x, b.y, b.z, b.w};
    uint4 hv, lv;
    __nv_bfloat16* hp = (__nv_bfloat16*)&hv;
    __nv_bfloat16* lp = (__nv_bfloat16*)&lv;
#pragma unroll
    for (int j = 0; j < 8; j++) {
        __nv_bfloat16 h = __float2bfloat16(v[j]);
        float r = v[j] - __bfloat162float(h);
        hp[j] = h;
        lp[j] = __float2bfloat16(r);
    }
    *(uint4*)(hi + i) = hv;
    *(uint4*)(lo + i) = lv;
}

// ================= split-precision GEMM via mma.sync (HMMA) =================
// C[M,N] = (Ah+Al)[M,K] @ (Bh+Bl)[N,K]^T + bias ; fp32 accumulation in registers.
// CTA = 128x128, 8 warps (2m x 4n), warp tile 64x32, BK = 64, 3-stage cp.async.
#define TILE_B   16384                 // one operand tile: 128 rows x 128B
#define STAGE_B  (4 * TILE_B)          // Ah, Al, Bh, Bl
#define NSTAGE   3
#define GEMM_SMEM (NSTAGE * STAGE_B)   // 196608

// swizzled 16B-chunk offset within one tile: row 0..127, chunk 0..7
__device__ __forceinline__ uint32_t swz(int row, int chunk) {
    return (uint32_t)((row * 8 + (chunk ^ (row & 7))) << 4);
}

__device__ __forceinline__ void load_stage(
    uint32_t sbase,
    const __nv_bfloat16* A0, const __nv_bfloat16* A1,
    const __nv_bfloat16* B0, const __nv_bfloat16* B1,
    int k0, int K, int tid)
{
    const int c  = tid & 7;        // 16B chunk within 128B row
    const int r0 = tid >> 3;       // 0..31
    const __nv_bfloat16* srcs[4] = {A0, A1, B0, B1};
#pragma unroll
    for (int t = 0; t < 4; t++) {
        const uint32_t tb = sbase + t * TILE_B;
        const __nv_bfloat16* sp = srcs[t] + k0 + c * 8;
#pragma unroll
        for (int i = 0; i < 4; i++) {
            int row = r0 + i * 32;
            uint32_t dst = tb + swz(row, c);
            CP_ASYNC16(dst, sp + (size_t)row * K);
        }
    }
}

__global__ __launch_bounds__(256) void gemm_mma_bf16x3(
    const __nv_bfloat16* __restrict__ Ah, const __nv_bfloat16* __restrict__ Al,
    const __nv_bfloat16* __restrict__ Bh, const __nv_bfloat16* __restrict__ Bl,
    const float* __restrict__ bias, float* __restrict__ C,
    int K, int N, int relu)
{
    extern __shared__ __align__(1024) char smem[];
    const uint32_t sb = smem_u32(smem);

    const int tid    = threadIdx.x;
    const int lane   = tid & 31;
    const int wid    = tid >> 5;
    const int warp_m = wid >> 2;     // 0..1
    const int warp_n = wid & 3;      // 0..3
    const int m0 = blockIdx.y * 128;
    const int n0 = blockIdx.x * 128;

    const __nv_bfloat16* A0 = Ah + (size_t)m0 * K;
    const __nv_bfloat16* A1 = Al + (size_t)m0 * K;
    const __nv_bfloat16* B0 = Bh + (size_t)n0 * K;
    const __nv_bfloat16* B1 = Bl + (size_t)n0 * K;

    const int S = K >> 6;

    load_stage(sb + 0 * STAGE_B, A0, A1, B0, B1, 0, K, tid);
    CP_COMMIT();
    load_stage(sb + 1 * STAGE_B, A0, A1, B0, B1, 64, K, tid);
    CP_COMMIT();

    float acc[4][4][4];
#pragma unroll
    for (int a = 0; a < 4; a++)
#pragma unroll
        for (int b = 0; b < 4; b++)
#pragma unroll
            for (int c = 0; c < 4; c++) acc[a][b][c] = 0.f;

    // lane-derived fragment addressing terms
    const int a_row_lo = (lane & 7) + (((lane >> 3) & 1) << 3);
    const int a_cbit   = (lane >> 4) & 1;
    const int b_row_lo = (lane & 7) + (((lane >> 4) & 1) << 3);
    const int b_cbit   = (lane >> 3) & 1;

    for (int kt = 0; kt < S; kt++) {
        CP_WAIT1();
        __syncthreads();
        if (kt + 2 < S) {
            load_stage(sb + ((kt + 2) % NSTAGE) * STAGE_B,
                       A0, A1, B0, B1, (kt + 2) * 64, K, tid);
        }
        CP_COMMIT();

        const uint32_t st = sb + (kt % NSTAGE) * STAGE_B;
        const uint32_t aAh = st;
        const uint32_t aAl = st + TILE_B;
        const uint32_t aBh = st + 2 * TILE_B;
        const uint32_t aBl = st + 3 * TILE_B;

#pragma unroll
        for (int ks = 0; ks < 4; ks++) {
            uint32_t ah[4][4], al[4][4];
#pragma unroll
            for (int mt = 0; mt < 4; mt++) {
                int row   = warp_m * 64 + mt * 16 + a_row_lo;
                int chunk = ks * 2 + a_cbit;
                uint32_t off = swz(row, chunk);
                ldsm4(ah[mt], aAh + off);
                ldsm4(al[mt], aAl + off);
            }
            uint32_t bh[2][4], bl[2][4];
#pragma unroll
            for (int bp = 0; bp < 2; bp++) {
                int row   = warp_n * 32 + bp * 16 + b_row_lo;
                int chunk = ks * 2 + b_cbit;
                uint32_t off = swz(row, chunk);
                ldsm4(bh[bp], aBh + off);
                ldsm4(bl[bp], aBl + off);
            }
#pragma unroll
            for (int mt = 0; mt < 4; mt++) {
#pragma unroll
                for (int nt = 0; nt < 4; nt++) {
                    uint32_t b0h = bh[nt >> 1][(nt & 1) * 2];
                    uint32_t b1h = bh[nt >> 1][(nt & 1) * 2 + 1];
                    uint32_t b0l = bl[nt >> 1][(nt & 1) * 2];
                    uint32_t b1l = bl[nt >> 1][(nt & 1) * 2 + 1];
                    mma16816(acc[mt][nt], ah[mt], b0h, b1h);
                    mma16816(acc[mt][nt], ah[mt], b0l, b1l);
                    mma16816(acc[mt][nt], al[mt], b0h, b1h);
                }
            }
        }
    }

    // epilogue: bias + optional ReLU, fp32 stores
    const int rbase = m0 + warp_m * 64 + (lane >> 2);
    const int cbase = n0 + warp_n * 32 + (lane & 3) * 2;
#pragma unroll
    for (int nt = 0; nt < 4; nt++) {
        int col = cbase + nt * 8;
        float bv0 = __ldg(bias + col);
        float bv1 = __ldg(bias + col + 1);
#pragma unroll
        for (int mt = 0; mt < 4; mt++) {
            int r = rbase + mt * 16;
            float c0 = acc[mt][nt][0] + bv0;
            float c1 = acc[mt][nt][1] + bv1;
            float c2 = acc[mt][nt][2] + bv0;
            float c3 = acc[mt][nt][3] + bv1;
            if (relu) {
                c0 = fmaxf(c0, 0.f); c1 = fmaxf(c1, 0.f);
                c2 = fmaxf(c2, 0.f); c3 = fmaxf(c3, 0.f);
            }
            float2 v0 = make_float2(c0, c1);
            float2 v1 = make_float2(c2, c3);
            *(float2*)(C + (size_t)r * N + col)       = v0;
            *(float2*)(C + (size_t)(r + 8) * N + col) = v1;
        }
    }
}

// ---------------- banded attention (unchanged) ----------------
#define ATTN_SMEM_FLOATS (QT * PITCH + 2 * KT * PITCH + QT * KT)
#define ATTN_SMEM_BYTES  (ATTN_SMEM_FLOATS * 4)

__global__ __launch_bounds__(256) void band_attn(
    const float* __restrict__ q, const float* __restrict__ k,
    const float* __restrict__ v, float* __restrict__ o)
{
    extern __shared__ float sm[];
    float* Qs = sm;
    float* Ks = Qs + QT * PITCH;
    float* Vs = Ks + KT * PITCH;
    float* Ss = Vs + KT * PITCH;

    const int t  = threadIdx.x;
    const int q0 = blockIdx.x * QT;
    const int h  = blockIdx.y;
    const int b  = blockIdx.z;
    const size_t hoff = (size_t)h * HEAD_DIM;

    for (int idx = t; idx < QT * 16; idx += 256) {
        int i  = idx >> 4;
        int d4 = (idx & 15) * 4;
        float4 val = *(const float4*)(q + ((size_t)(b * SEQ + q0 + i) * EMBED) + hoff + d4);
        Qs[i * PITCH + d4 + 0] = val.x;
        Qs[i * PITCH + d4 + 1] = val.y;
        Qs[i * PITCH + d4 + 2] = val.z;
        Qs[i * PITCH + d4 + 3] = val.w;
    }
    for (int idx = t; idx < KT * 16; idx += 256) {
        int jj = idx >> 4;
        int d4 = (idx & 15) * 4;
        int j  = q0 - BANDW + jj;
        float4 kv = make_float4(0.f, 0.f, 0.f, 0.f);
        float4 vv = make_float4(0.f, 0.f, 0.f, 0.f);
        if (j >= 0 && j < SEQ) {
            size_t base = ((size_t)(b * SEQ + j) * EMBED) + hoff + d4;
            kv = *(const float4*)(k + base);
            vv = *(const float4*)(v + base);
        }
        Ks[jj * PITCH + d4 + 0] = kv.x;
        Ks[jj * PITCH + d4 + 1] = kv.y;
        Ks[jj * PITCH + d4 + 2] = kv.z;
        Ks[jj * PITCH + d4 + 3] = kv.w;
        Vs[jj * PITCH + d4 + 0] = vv.x;
        Vs[jj * PITCH + d4 + 1] = vv.y;
        Vs[jj * PITCH + d4 + 2] = vv.z;
        Vs[jj * PITCH + d4 + 3] = vv.w;
    }
    __syncthreads();

    const float scale = 0.125f;
    const int i  = t >> 2;
    const int jl = t & 3;
    for (int jj = jl; jj < KT; jj += 4) {
        int j = q0 - BANDW + jj;
        float sres = -1e9f;
        if (jj >= i && jj <= i + 2 * BANDW && j >= 0 && j < SEQ) {
            const float4* qp = (const float4*)(Qs + i * PITCH);
            const float4* kp = (const float4*)(Ks + jj * PITCH);
            float accv = 0.f;
#pragma unroll
            for (int d4 = 0; d4 < 16; d4++) {
                float4 aa = qp[d4], cc = kp[d4];
                accv += aa.x * cc.x + aa.y * cc.y + aa.z * cc.z + aa.w * cc.w;
            }
            sres = accv * scale;
        }
        Ss[i * KT + jj] = sres;
    }
    __syncthreads();

    if (t < QT) {
        float* srow = Ss + t * KT;
        float mx = -1e30f;
        for (int jj = 0; jj < KT; jj++) mx = fmaxf(mx, srow[jj]);
        float sum = 0.f;
        for (int jj = 0; jj < KT; jj++) {
            float e = expf(srow[jj] - mx);
            srow[jj] = e;
            sum += e;
        }
        float inv = 1.f / sum;
        for (int jj = 0; jj < KT; jj++) srow[jj] *= inv;
    }
    __syncthreads();

    const int dblk = (t & 3) * 16;
    float acc[16];
#pragma unroll
    for (int kk = 0; kk < 16; kk++) acc[kk] = 0.f;
    for (int jj = 0; jj < KT; jj++) {
        float p = Ss[i * KT + jj];
        const float4* vp = (const float4*)(Vs + jj * PITCH + dblk);
#pragma unroll
        for (int k4 = 0; k4 < 4; k4++) {
            float4 vv = vp[k4];
            acc[k4 * 4 + 0] += p * vv.x;
            acc[k4 * 4 + 1] += p * vv.y;
            acc[k4 * 4 + 2] += p * vv.z;
            acc[k4 * 4 + 3] += p * vv.w;
        }
    }
    float* op = o + ((size_t)(b * SEQ + q0 + i) * EMBED) + hoff + dblk;
#pragma unroll
    for (int k4 = 0; k4 < 4; k4++) {
        float4 r;
        r.x = acc[k4 * 4 + 0];
        r.y = acc[k4 * 4 + 1];
        r.z = acc[k4 * 4 + 2];
        r.w = acc[k4 * 4 + 3];
        *(float4*)(op + k4 * 4) = r;
    }
}

// ---------------- fused residual add + LayerNorm (unchanged) ----------------
__global__ __launch_bounds__(256) void add_ln(
    const float* __restrict__ r, const float* __restrict__ p,
    const float* __restrict__ g, const float* __restrict__ be,
    float* __restrict__ y)
{
    const int row = blockIdx.x;
    const int t = threadIdx.x;
    const size_t base = (size_t)row * EMBED + t * 4;
    float4 rv = *(const float4*)(r + base);
    float4 pv = *(const float4*)(p + base);
    float z0 = rv.x + pv.x, z1 = rv.y + pv.y, z2 = rv.z + pv.z, z3 = rv.w + pv.w;
    float s  = z0 + z1 + z2 + z3;
    float sq = z0 * z0 + z1 * z1 + z2 * z2 + z3 * z3;
#pragma unroll
    for (int off = 16; off > 0; off >>= 1) {
        s  += __shfl_xor_sync(0xffffffffu, s, off);
        sq += __shfl_xor_sync(0xffffffffu, sq, off);
    }
    __shared__ float ws[8], wsq[8];
    __shared__ float mu_s, rstd_s;
    const int warp = t >> 5, lane = t & 31;
    if (lane == 0) { ws[warp] = s; wsq[warp] = sq; }
    __syncthreads();
    if (t == 0) {
        float ts = 0.f, tsq = 0.f;
#pragma unroll
        for (int wdx = 0; wdx < 8; wdx++) { ts += ws[wdx]; tsq += wsq[wdx]; }
        float mu = ts * (1.f / EMBED);
        float var = tsq * (1.f / EMBED) - mu * mu;
        mu_s = mu;
        rstd_s = rsqrtf(var + 1e-5f);
    }
    __syncthreads();
    float mu = mu_s, rstd = rstd_s;
    float4 gv = *(const float4*)(g + t * 4);
    float4 bv = *(const float4*)(be + t * 4);
    float4 out;
    out.x = (z0 - mu) * rstd * gv.x + bv.x;
    out.y = (z1 - mu) * rstd * gv.y + bv.y;
    out.z = (z2 - mu) * rstd * gv.z + bv.z;
    out.w = (z3 - mu) * rstd * gv.w + bv.w;
    *(float4*)(y + base) = out;
}

// ---------------- launch ----------------
static inline void conv(const float* in, __nv_bfloat16* hi, __nv_bfloat16* lo, int n) {
    convert_split<<<n / 2048, 256>>>(in, hi, lo, n);
}

extern "C" void kernel_launch(void* const* d_in, const int* in_sizes, int n_in,
                              void* d_out, int out_size)
{
    static bool inited = false;
    static float *pq, *pk, *pv, *pattn, *pproj, *px, *px2, *pff;
    static __nv_bfloat16 *pah, *pal, *pfh, *pfl, *pwh, *pwl;
    if (!inited) {
        cudaGetSymbolAddress((void**)&pq,    g_q);
        cudaGetSymbolAddress((void**)&pk,    g_k);
        cudaGetSymbolAddress((void**)&pv,    g_v);
        cudaGetSymbolAddress((void**)&pattn, g_attn);
        cudaGetSymbolAddress((void**)&pproj, g_proj);
        cudaGetSymbolAddress((void**)&px,    g_x);
        cudaGetSymbolAddress((void**)&px2,   g_x2);
        cudaGetSymbolAddress((void**)&pff,   g_ffbuf);
        cudaGetSymbolAddress((void**)&pah,   g_ah);
        cudaGetSymbolAddress((void**)&pal,   g_al);
        cudaGetSymbolAddress((void**)&pfh,   g_fh);
        cudaGetSymbolAddress((void**)&pfl,   g_fl);
        cudaGetSymbolAddress((void**)&pwh,   g_wh);
        cudaGetSymbolAddress((void**)&pwl,   g_wl);
        cudaFuncSetAttribute(band_attn, cudaFuncAttributeMaxDynamicSharedMemorySize,
                             ATTN_SMEM_BYTES);
        cudaFuncSetAttribute(gemm_mma_bf16x3, cudaFuncAttributeMaxDynamicSharedMemorySize,
                             GEMM_SMEM);
        inited = true;
    }

    const float* x   = (const float*)d_in[0];
    const float* Wq  = (const float*)d_in[1];
    const float* bq  = (const float*)d_in[2];
    const float* Wk  = (const float*)d_in[3];
    const float* bk  = (const float*)d_in[4];
    const float* Wv  = (const float*)d_in[5];
    const float* bv  = (const float*)d_in[6];
    const float* Wo  = (const float*)d_in[7];
    const float* bo  = (const float*)d_in[8];
    const float* W1  = (const float*)d_in[9];
    const float* b1  = (const float*)d_in[10];
    const float* W2  = (const float*)d_in[11];
    const float* b2  = (const float*)d_in[12];
    const float* g1  = (const float*)d_in[13];
    const float* be1 = (const float*)d_in[14];
    const float* g2  = (const float*)d_in[15];
    const float* be2 = (const float*)d_in[16];
    float* out = (float*)d_out;

    const dim3 gE(EMBED / 128, ROWS / 128);   // (8, 32)
    const dim3 gF(FFDIM / 128, ROWS / 128);   // (32, 32)
    const dim3 gA(SEQ / QT, HEADS, BATCH);    // (32, 16, 2)

    const float* cur = x;
    for (int L = 0; L < LAYERS; L++) {
        const size_t oEE = (size_t)L * EMBED * EMBED;
        const size_t oE  = (size_t)L * EMBED;
        const size_t oFE = (size_t)L * FFDIM * EMBED;
        const size_t oF  = (size_t)L * FFDIM;

        // ---- attention projections (shared activation split) ----
        conv(cur, pah, pal, ROWS * EMBED);

        conv(Wq + oEE, pwh, pwl, EMBED * EMBED);
        gemm_mma_bf16x3<<<gE, 256, GEMM_SMEM>>>(pah, pal, pwh, pwl,
                                                bq + oE, pq, EMBED, EMBED, 0);
        conv(Wk + oEE, pwh, pwl, EMBED * EMBED);
        gemm_mma_bf16x3<<<gE, 256, GEMM_SMEM>>>(pah, pal, pwh, pwl,
                                                bk + oE, pk, EMBED, EMBED, 0);
        conv(Wv + oEE, pwh, pwl, EMBED * EMBED);
        gemm_mma_bf16x3<<<gE, 256, GEMM_SMEM>>>(pah, pal, pwh, pwl,
                                                bv + oE, pv, EMBED, EMBED, 0);

        band_attn<<<gA, 256, ATTN_SMEM_BYTES>>>(pq, pk, pv, pattn);

        conv(pattn, pah, pal, ROWS * EMBED);
        conv(Wo + oEE, pwh, pwl, EMBED * EMBED);
        gemm_mma_bf16x3<<<gE, 256, GEMM_SMEM>>>(pah, pal, pwh, pwl,
                                                bo + oE, pproj, EMBED, EMBED, 0);

        add_ln<<<ROWS, 256>>>(cur, pproj, g1 + oE, be1 + oE, px2);

        // ---- FF ----
        conv(px2, pah, pal, ROWS * EMBED);
        conv(W1 + oFE, pwh, pwl, FFDIM * EMBED);
        gemm_mma_bf16x3<<<gF, 256, GEMM_SMEM>>>(pah, pal, pwh, pwl,
                                                b1 + oF, pff, EMBED, FFDIM, 1);

        conv(pff, pfh, pfl, ROWS * FFDIM);
        conv(W2 + oFE, pwh, pwl, FFDIM * EMBED);
        gemm_mma_bf16x3<<<gE, 256, GEMM_SMEM>>>(pfh, pfl, pwh, pwl,
                                                b2 + oE, pproj, FFDIM, EMBED, 0);

        float* dst = (L == LAYERS - 1) ? out : px;
        add_ln<<<ROWS, 256>>>(px2, pproj, g2 + oE, be2 + oE, dst);
        cur = px;
    }
}

// round 15
// speedup vs baseline: 2.3774x; 1.1073x over previous
#include <cuda_runtime.h>
#include <cuda_bf16.h>
#include <math.h>
#include <stdint.h>

// ---------------- problem constants ----------------
#define EMBED    1024
#define HEADS    16
#define HEAD_DIM 64
#define FFDIM    4096
#define LAYERS   4
#define BATCH    2
#define SEQ      2048
#define ROWS     (BATCH * SEQ)   // 4096
#define BANDW    46              // ceil(sqrt(2048))

// attention tiling
#define QT    64
#define KT    (QT + 2 * BANDW)   // 156
#define PITCH 68                 // padded row pitch (floats) for K/V smem
#define SBW   97                 // band score slots per row (93 used, 97 kills bank conflicts)

// ---------------- scratch (device globals; no allocation allowed) ----------------
__device__ __align__(256) float g_q[ROWS * EMBED];
__device__ __align__(256) float g_k[ROWS * EMBED];
__device__ __align__(256) float g_v[ROWS * EMBED];
__device__ __align__(256) float g_attn[ROWS * EMBED];
__device__ __align__(256) float g_proj[ROWS * EMBED];
__device__ __align__(256) float g_x[ROWS * EMBED];
__device__ __align__(256) float g_x2[ROWS * EMBED];
__device__ __align__(256) float g_ffbuf[ROWS * FFDIM];

// split-precision bf16 operand buffers
__device__ __align__(256) __nv_bfloat16 g_ah[ROWS * EMBED];
__device__ __align__(256) __nv_bfloat16 g_al[ROWS * EMBED];
__device__ __align__(256) __nv_bfloat16 g_fh[ROWS * FFDIM];
__device__ __align__(256) __nv_bfloat16 g_fl[ROWS * FFDIM];
// per-stream weight buffers
__device__ __align__(256) __nv_bfloat16 g_wh[EMBED * EMBED];    // Wq / Wo (stream 0)
__device__ __align__(256) __nv_bfloat16 g_wl[EMBED * EMBED];
__device__ __align__(256) __nv_bfloat16 g_wkh[EMBED * EMBED];   // Wk (stream 1)
__device__ __align__(256) __nv_bfloat16 g_wkl[EMBED * EMBED];
__device__ __align__(256) __nv_bfloat16 g_wvh[EMBED * EMBED];   // Wv (stream 2)
__device__ __align__(256) __nv_bfloat16 g_wvl[EMBED * EMBED];
__device__ __align__(256) __nv_bfloat16 g_w1h[FFDIM * EMBED];   // W1 (stream 1)
__device__ __align__(256) __nv_bfloat16 g_w1l[FFDIM * EMBED];
__device__ __align__(256) __nv_bfloat16 g_w2h[FFDIM * EMBED];   // W2 (stream 2)
__device__ __align__(256) __nv_bfloat16 g_w2l[FFDIM * EMBED];

// ================= helpers =================
__device__ __forceinline__ uint32_t smem_u32(const void* p) {
    uint32_t a;
    asm("{ .reg .u64 t; cvta.to.shared.u64 t, %1; cvt.u32.u64 %0, t; }"
        : "=r"(a) : "l"(p));
    return a;
}

__device__ __forceinline__ void ldsm4(uint32_t r[4], uint32_t addr) {
    asm volatile("ldmatrix.sync.aligned.m8n8.x4.shared.b16 {%0,%1,%2,%3}, [%4];"
                 : "=r"(r[0]), "=r"(r[1]), "=r"(r[2]), "=r"(r[3]) : "r"(addr));
}

__device__ __forceinline__ void mma16816(float c[4], const uint32_t a[4],
                                         uint32_t b0, uint32_t b1) {
    asm volatile(
        "mma.sync.aligned.m16n8k16.row.col.f32.bf16.bf16.f32 "
        "{%0,%1,%2,%3}, {%4,%5,%6,%7}, {%8,%9}, {%0,%1,%2,%3};"
        : "+f"(c[0]), "+f"(c[1]), "+f"(c[2]), "+f"(c[3])
        : "r"(a[0]), "r"(a[1]), "r"(a[2]), "r"(a[3]), "r"(b0), "r"(b1));
}

#define CP_ASYNC16(dst, src) \
    asm volatile("cp.async.cg.shared.global [%0], [%1], 16;" :: "r"(dst), "l"(src))
#define CP_COMMIT() asm volatile("cp.async.commit_group;" ::: "memory")
#define CP_WAIT1()  asm volatile("cp.async.wait_group 1;" ::: "memory")

// ================= split conversion: fp32 -> (bf16 hi, bf16 lo) =================
__global__ __launch_bounds__(256) void convert_split(
    const float* __restrict__ in, __nv_bfloat16* __restrict__ hi,
    __nv_bfloat16* __restrict__ lo, int n)
{
    int i = (blockIdx.x * 256 + threadIdx.x) * 8;
    if (i >= n) return;
    float4 a = *(const float4*)(in + i);
    float4 b = *(const float4*)(in + i + 4);
    float v[8] = {a.x, a.y, a.z, a.w, b.x, b.y, b.z, b.w};
    uint4 hv, lv;
    __nv_bfloat16* hp = (__nv_bfloat16*)&hv;
    __nv_bfloat16* lp = (__nv_bfloat16*)&lv;
#pragma unroll
    for (int j = 0; j < 8; j++) {
        __nv_bfloat16 h = __float2bfloat16(v[j]);
        float r = v[j] - __bfloat162float(h);
        hp[j] = h;
        lp[j] = __float2bfloat16(r);
    }
    *(uint4*)(hi + i) = hv;
    *(uint4*)(lo + i) = lv;
}

// ================= split-precision GEMM via mma.sync (HMMA) =================
// C[M,N] = (Ah+Al)[M,K] @ (Bh+Bl)[N,K]^T + bias ; fp32 accumulation in registers.
// CTA = 128x128, 8 warps (2m x 4n), warp tile 64x32, BK = 64, 3-stage cp.async.
#define TILE_B   16384                 // one operand tile: 128 rows x 128B
#define STAGE_B  (4 * TILE_B)          // Ah, Al, Bh, Bl
#define NSTAGE   3
#define GEMM_SMEM (NSTAGE * STAGE_B)   // 196608

// swizzled 16B-chunk offset within one tile: row 0..127, chunk 0..7
__device__ __forceinline__ uint32_t swz(int row, int chunk) {
    return (uint32_t)((row * 8 + (chunk ^ (row & 7))) << 4);
}

__device__ __forceinline__ void load_stage(
    uint32_t sbase,
    const __nv_bfloat16* A0, const __nv_bfloat16* A1,
    const __nv_bfloat16* B0, const __nv_bfloat16* B1,
    int k0, int K, int tid)
{
    const int c  = tid & 7;        // 16B chunk within 128B row
    const int r0 = tid >> 3;       // 0..31
    const __nv_bfloat16* srcs[4] = {A0, A1, B0, B1};
#pragma unroll
    for (int t = 0; t < 4; t++) {
        const uint32_t tb = sbase + t * TILE_B;
        const __nv_bfloat16* sp = srcs[t] + k0 + c * 8;
#pragma unroll
        for (int i = 0; i < 4; i++) {
            int row = r0 + i * 32;
            uint32_t dst = tb + swz(row, c);
            CP_ASYNC16(dst, sp + (size_t)row * K);
        }
    }
}

__global__ __launch_bounds__(256) void gemm_mma_bf16x3(
    const __nv_bfloat16* __restrict__ Ah, const __nv_bfloat16* __restrict__ Al,
    const __nv_bfloat16* __restrict__ Bh, const __nv_bfloat16* __restrict__ Bl,
    const float* __restrict__ bias, float* __restrict__ C,
    int K, int N, int relu)
{
    extern __shared__ __align__(1024) char smem[];
    const uint32_t sb = smem_u32(smem);

    const int tid    = threadIdx.x;
    const int lane   = tid & 31;
    const int wid    = tid >> 5;
    const int warp_m = wid >> 2;     // 0..1
    const int warp_n = wid & 3;      // 0..3
    const int m0 = blockIdx.y * 128;
    const int n0 = blockIdx.x * 128;

    const __nv_bfloat16* A0 = Ah + (size_t)m0 * K;
    const __nv_bfloat16* A1 = Al + (size_t)m0 * K;
    const __nv_bfloat16* B0 = Bh + (size_t)n0 * K;
    const __nv_bfloat16* B1 = Bl + (size_t)n0 * K;

    const int S = K >> 6;

    load_stage(sb + 0 * STAGE_B, A0, A1, B0, B1, 0, K, tid);
    CP_COMMIT();
    load_stage(sb + 1 * STAGE_B, A0, A1, B0, B1, 64, K, tid);
    CP_COMMIT();

    float acc[4][4][4];
#pragma unroll
    for (int a = 0; a < 4; a++)
#pragma unroll
        for (int b = 0; b < 4; b++)
#pragma unroll
            for (int c = 0; c < 4; c++) acc[a][b][c] = 0.f;

    // lane-derived fragment addressing terms
    const int a_row_lo = (lane & 7) + (((lane >> 3) & 1) << 3);
    const int a_cbit   = (lane >> 4) & 1;
    const int b_row_lo = (lane & 7) + (((lane >> 4) & 1) << 3);
    const int b_cbit   = (lane >> 3) & 1;

    for (int kt = 0; kt < S; kt++) {
        CP_WAIT1();
        __syncthreads();
        if (kt + 2 < S) {
            load_stage(sb + ((kt + 2) % NSTAGE) * STAGE_B,
                       A0, A1, B0, B1, (kt + 2) * 64, K, tid);
        }
        CP_COMMIT();

        const uint32_t st = sb + (kt % NSTAGE) * STAGE_B;
        const uint32_t aAh = st;
        const uint32_t aAl = st + TILE_B;
        const uint32_t aBh = st + 2 * TILE_B;
        const uint32_t aBl = st + 3 * TILE_B;

#pragma unroll
        for (int ks = 0; ks < 4; ks++) {
            uint32_t ah[4][4], al[4][4];
#pragma unroll
            for (int mt = 0; mt < 4; mt++) {
                int row   = warp_m * 64 + mt * 16 + a_row_lo;
                int chunk = ks * 2 + a_cbit;
                uint32_t off = swz(row, chunk);
                ldsm4(ah[mt], aAh + off);
                ldsm4(al[mt], aAl + off);
            }
            uint32_t bh[2][4], bl[2][4];
#pragma unroll
            for (int bp = 0; bp < 2; bp++) {
                int row   = warp_n * 32 + bp * 16 + b_row_lo;
                int chunk = ks * 2 + b_cbit;
                uint32_t off = swz(row, chunk);
                ldsm4(bh[bp], aBh + off);
                ldsm4(bl[bp], aBl + off);
            }
#pragma unroll
            for (int mt = 0; mt < 4; mt++) {
#pragma unroll
                for (int nt = 0; nt < 4; nt++) {
                    uint32_t b0h = bh[nt >> 1][(nt & 1) * 2];
                    uint32_t b1h = bh[nt >> 1][(nt & 1) * 2 + 1];
                    uint32_t b0l = bl[nt >> 1][(nt & 1) * 2];
                    uint32_t b1l = bl[nt >> 1][(nt & 1) * 2 + 1];
                    mma16816(acc[mt][nt], ah[mt], b0h, b1h);
                    mma16816(acc[mt][nt], ah[mt], b0l, b1l);
                    mma16816(acc[mt][nt], al[mt], b0h, b1h);
                }
            }
        }
    }

    // epilogue: bias + optional ReLU, fp32 stores
    const int rbase = m0 + warp_m * 64 + (lane >> 2);
    const int cbase = n0 + warp_n * 32 + (lane & 3) * 2;
#pragma unroll
    for (int nt = 0; nt < 4; nt++) {
        int col = cbase + nt * 8;
        float bv0 = __ldg(bias + col);
        float bv1 = __ldg(bias + col + 1);
#pragma unroll
        for (int mt = 0; mt < 4; mt++) {
            int r = rbase + mt * 16;
            float c0 = acc[mt][nt][0] + bv0;
            float c1 = acc[mt][nt][1] + bv1;
            float c2 = acc[mt][nt][2] + bv0;
            float c3 = acc[mt][nt][3] + bv1;
            if (relu) {
                c0 = fmaxf(c0, 0.f); c1 = fmaxf(c1, 0.f);
                c2 = fmaxf(c2, 0.f); c3 = fmaxf(c3, 0.f);
            }
            float2 v0 = make_float2(c0, c1);
            float2 v1 = make_float2(c2, c3);
            *(float2*)(C + (size_t)r * N + col)       = v0;
            *(float2*)(C + (size_t)(r + 8) * N + col) = v1;
        }
    }
}

// ---------------- banded attention, v2 ----------------
// One CTA per (batch, head, 64-query tile). 2 CTAs/SM (109.7KB smem).
// Q rows live in registers; score/AV loops cover only the true band s in [0,92];
// scores stored band-relative (64 x 97); 4-lane shfl softmax.
#define ATTN_SMEM_FLOATS (2 * KT * PITCH + QT * SBW)
#define ATTN_SMEM_BYTES  (ATTN_SMEM_FLOATS * 4)

__global__ __launch_bounds__(256, 2) void band_attn(
    const float* __restrict__ q, const float* __restrict__ k,
    const float* __restrict__ v, float* __restrict__ o)
{
    extern __shared__ float sm[];
    float* Ks = sm;                       // KT * PITCH
    float* Vs = Ks + KT * PITCH;          // KT * PITCH
    float* Ss = Vs + KT * PITCH;          // QT * SBW

    const int t  = threadIdx.x;           // 256
    const int q0 = blockIdx.x * QT;
    const int h  = blockIdx.y;
    const int b  = blockIdx.z;
    const size_t hoff = (size_t)h * HEAD_DIM;

    const int i  = t >> 2;                // query row 0..63
    const int jl = t & 3;                 // lane-within-row 0..3

    // load K/V window into smem (zero-fill outside sequence)
    for (int idx = t; idx < KT * 16; idx += 256) {
        int jj = idx >> 4;
        int d4 = (idx & 15) * 4;
        int j  = q0 - BANDW + jj;
        float4 kv = make_float4(0.f, 0.f, 0.f, 0.f);
        float4 vv = make_float4(0.f, 0.f, 0.f, 0.f);
        if (j >= 0 && j < SEQ) {
            size_t base = ((size_t)(b * SEQ + j) * EMBED) + hoff + d4;
            kv = *(const float4*)(k + base);
            vv = *(const float4*)(v + base);
        }
        Ks[jj * PITCH + d4 + 0] = kv.x;
        Ks[jj * PITCH + d4 + 1] = kv.y;
        Ks[jj * PITCH + d4 + 2] = kv.z;
        Ks[jj * PITCH + d4 + 3] = kv.w;
        Vs[jj * PITCH + d4 + 0] = vv.x;
        Vs[jj * PITCH + d4 + 1] = vv.y;
        Vs[jj * PITCH + d4 + 2] = vv.z;
        Vs[jj * PITCH + d4 + 3] = vv.w;
    }

    // Q row -> registers (redundant x4 across jl; tiny volume, L1 hits)
    float qreg[64];
    {
        const float* qrow = q + ((size_t)(b * SEQ + q0 + i) * EMBED) + hoff;
#pragma unroll
        for (int d4 = 0; d4 < 16; d4++) {
            float4 val = __ldg((const float4*)qrow + d4);
            qreg[d4 * 4 + 0] = val.x;
            qreg[d4 * 4 + 1] = val.y;
            qreg[d4 * 4 + 2] = val.z;
            qreg[d4 * 4 + 3] = val.w;
        }
    }
    __syncthreads();

    // scores, band-restricted: s = jj - i in [0, 92]
    const float scale = 0.125f;  // 1/sqrt(64)
    for (int s = jl; s <= 92; s += 4) {
        int jj = i + s;
        int j  = q0 - BANDW + jj;
        float sc = -1e9f;
        if (j >= 0 && j < SEQ) {
            const float* kp = Ks + jj * PITCH;
            float a0 = 0.f, a1 = 0.f, a2 = 0.f, a3 = 0.f;
#pragma unroll
            for (int d4 = 0; d4 < 16; d4++) {
                float4 kk = *(const float4*)(kp + d4 * 4);
                a0 += qreg[d4 * 4 + 0] * kk.x;
                a1 += qreg[d4 * 4 + 1] * kk.y;
                a2 += qreg[d4 * 4 + 2] * kk.z;
                a3 += qreg[d4 * 4 + 3] * kk.w;
            }
            sc = (a0 + a1 + a2 + a3) * scale;
        }
        Ss[i * SBW + s] = sc;
    }
    __syncthreads();

    // softmax: 4 lanes per row, contiguous slot ranges, shfl combine
    {
        float* srow = Ss + i * SBW;
        const int lo = jl * 24;
        const int hi = (jl == 3) ? 93 : lo + 24;
        float mx = -1e30f;
        for (int s = lo; s < hi; s++) mx = fmaxf(mx, srow[s]);
        mx = fmaxf(mx, __shfl_xor_sync(0xffffffffu, mx, 1));
        mx = fmaxf(mx, __shfl_xor_sync(0xffffffffu, mx, 2));
        float sum = 0.f;
        for (int s = lo; s < hi; s++) {
            float e = expf(srow[s] - mx);
            srow[s] = e;
            sum += e;
        }
        sum += __shfl_xor_sync(0xffffffffu, sum, 1);
        sum += __shfl_xor_sync(0xffffffffu, sum, 2);
        float inv = 1.f / sum;
        for (int s = lo; s < hi; s++) srow[s] *= inv;
    }
    __syncthreads();

    // AV: thread (i, c) handles dims [c*16, c*16+16), band-restricted.
    // chunk order (k4 + (c&2)) & 3 makes the 8-lane phases bank-conflict-free.
    const int c = jl;
    float acc[16];
#pragma unroll
    for (int kk = 0; kk < 16; kk++) acc[kk] = 0.f;
    const float* prow = Ss + i * SBW;
    for (int s = 0; s <= 92; s++) {
        int jj = i + s;
        float p = prow[s];
        const float* vp = Vs + jj * PITCH + c * 16;
#pragma unroll
        for (int k4 = 0; k4 < 4; k4++) {
            int ch = (k4 + (c & 2)) & 3;
            float4 vv = *(const float4*)(vp + ch * 4);
            acc[ch * 4 + 0] += p * vv.x;
            acc[ch * 4 + 1] += p * vv.y;
            acc[ch * 4 + 2] += p * vv.z;
            acc[ch * 4 + 3] += p * vv.w;
        }
    }
    float* op = o + ((size_t)(b * SEQ + q0 + i) * EMBED) + hoff + c * 16;
#pragma unroll
    for (int k4 = 0; k4 < 4; k4++) {
        float4 r;
        r.x = acc[k4 * 4 + 0];
        r.y = acc[k4 * 4 + 1];
        r.z = acc[k4 * 4 + 2];
        r.w = acc[k4 * 4 + 3];
        *(float4*)(op + k4 * 4) = r;
    }
}

// ---------------- fused residual add + LayerNorm ----------------
__global__ __launch_bounds__(256) void add_ln(
    const float* __restrict__ r, const float* __restrict__ p,
    const float* __restrict__ g, const float* __restrict__ be,
    float* __restrict__ y)
{
    const int row = blockIdx.x;
    const int t = threadIdx.x;
    const size_t base = (size_t)row * EMBED + t * 4;
    float4 rv = *(const float4*)(r + base);
    float4 pv = *(const float4*)(p + base);
    float z0 = rv.x + pv.x, z1 = rv.y + pv.y, z2 = rv.z + pv.z, z3 = rv.w + pv.w;
    float s  = z0 + z1 + z2 + z3;
    float sq = z0 * z0 + z1 * z1 + z2 * z2 + z3 * z3;
#pragma unroll
    for (int off = 16; off > 0; off >>= 1) {
        s  += __shfl_xor_sync(0xffffffffu, s, off);
        sq += __shfl_xor_sync(0xffffffffu, sq, off);
    }
    __shared__ float ws[8], wsq[8];
    __shared__ float mu_s, rstd_s;
    const int warp = t >> 5, lane = t & 31;
    if (lane == 0) { ws[warp] = s; wsq[warp] = sq; }
    __syncthreads();
    if (t == 0) {
        float ts = 0.f, tsq = 0.f;
#pragma unroll
        for (int wdx = 0; wdx < 8; wdx++) { ts += ws[wdx]; tsq += wsq[wdx]; }
        float mu = ts * (1.f / EMBED);
        float var = tsq * (1.f / EMBED) - mu * mu;
        mu_s = mu;
        rstd_s = rsqrtf(var + 1e-5f);
    }
    __syncthreads();
    float mu = mu_s, rstd = rstd_s;
    float4 gv = *(const float4*)(g + t * 4);
    float4 bv = *(const float4*)(be + t * 4);
    float4 out;
    out.x = (z0 - mu) * rstd * gv.x + bv.x;
    out.y = (z1 - mu) * rstd * gv.y + bv.y;
    out.z = (z2 - mu) * rstd * gv.z + bv.z;
    out.w = (z3 - mu) * rstd * gv.w + bv.w;
    *(float4*)(y + base) = out;
}

// ---------------- launch ----------------
static inline void conv(const float* in, __nv_bfloat16* hi, __nv_bfloat16* lo,
                        int n, cudaStream_t st) {
    convert_split<<<n / 2048, 256, 0, st>>>(in, hi, lo, n);
}

extern "C" void kernel_launch(void* const* d_in, const int* in_sizes, int n_in,
                              void* d_out, int out_size)
{
    static bool inited = false;
    static float *pq, *pk, *pv, *pattn, *pproj, *px, *px2, *pff;
    static __nv_bfloat16 *pah, *pal, *pfh, *pfl;
    static __nv_bfloat16 *pwh, *pwl, *pwkh, *pwkl, *pwvh, *pwvl;
    static __nv_bfloat16 *pw1h, *pw1l, *pw2h, *pw2l;
    static cudaStream_t st1, st2;
    static cudaEvent_t ev0, evK, evV, evW1, evW2;
    if (!inited) {
        cudaGetSymbolAddress((void**)&pq,    g_q);
        cudaGetSymbolAddress((void**)&pk,    g_k);
        cudaGetSymbolAddress((void**)&pv,    g_v);
        cudaGetSymbolAddress((void**)&pattn, g_attn);
        cudaGetSymbolAddress((void**)&pproj, g_proj);
        cudaGetSymbolAddress((void**)&px,    g_x);
        cudaGetSymbolAddress((void**)&px2,   g_x2);
        cudaGetSymbolAddress((void**)&pff,   g_ffbuf);
        cudaGetSymbolAddress((void**)&pah,   g_ah);
        cudaGetSymbolAddress((void**)&pal,   g_al);
        cudaGetSymbolAddress((void**)&pfh,   g_fh);
        cudaGetSymbolAddress((void**)&pfl,   g_fl);
        cudaGetSymbolAddress((void**)&pwh,   g_wh);
        cudaGetSymbolAddress((void**)&pwl,   g_wl);
        cudaGetSymbolAddress((void**)&pwkh,  g_wkh);
        cudaGetSymbolAddress((void**)&pwkl,  g_wkl);
        cudaGetSymbolAddress((void**)&pwvh,  g_wvh);
        cudaGetSymbolAddress((void**)&pwvl,  g_wvl);
        cudaGetSymbolAddress((void**)&pw1h,  g_w1h);
        cudaGetSymbolAddress((void**)&pw1l,  g_w1l);
        cudaGetSymbolAddress((void**)&pw2h,  g_w2h);
        cudaGetSymbolAddress((void**)&pw2l,  g_w2l);
        cudaFuncSetAttribute(band_attn, cudaFuncAttributeMaxDynamicSharedMemorySize,
                             ATTN_SMEM_BYTES);
        cudaFuncSetAttribute(gemm_mma_bf16x3, cudaFuncAttributeMaxDynamicSharedMemorySize,
                             GEMM_SMEM);
        cudaStreamCreateWithFlags(&st1, cudaStreamNonBlocking);
        cudaStreamCreateWithFlags(&st2, cudaStreamNonBlocking);
        cudaEventCreateWithFlags(&ev0,  cudaEventDisableTiming);
        cudaEventCreateWithFlags(&evK,  cudaEventDisableTiming);
        cudaEventCreateWithFlags(&evV,  cudaEventDisableTiming);
        cudaEventCreateWithFlags(&evW1, cudaEventDisableTiming);
        cudaEventCreateWithFlags(&evW2, cudaEventDisableTiming);
        inited = true;
    }

    const float* x   = (const float*)d_in[0];
    const float* Wq  = (const float*)d_in[1];
    const float* bq  = (const float*)d_in[2];
    const float* Wk  = (const float*)d_in[3];
    const float* bk  = (const float*)d_in[4];
    const float* Wv  = (const float*)d_in[5];
    const float* bv  = (const float*)d_in[6];
    const float* Wo  = (const float*)d_in[7];
    const float* bo  = (const float*)d_in[8];
    const float* W1  = (const float*)d_in[9];
    const float* b1  = (const float*)d_in[10];
    const float* W2  = (const float*)d_in[11];
    const float* b2  = (const float*)d_in[12];
    const float* g1  = (const float*)d_in[13];
    const float* be1 = (const float*)d_in[14];
    const float* g2  = (const float*)d_in[15];
    const float* be2 = (const float*)d_in[16];
    float* out = (float*)d_out;

    const dim3 gE(EMBED / 128, ROWS / 128);   // (8, 32)
    const dim3 gF(FFDIM / 128, ROWS / 128);   // (32, 32)
    const dim3 gA(SEQ / QT, HEADS, BATCH);    // (32, 16, 2)
    cudaStream_t s0 = 0;

    const float* cur = x;
    for (int L = 0; L < LAYERS; L++) {
        const size_t oEE = (size_t)L * EMBED * EMBED;
        const size_t oE  = (size_t)L * EMBED;
        const size_t oFE = (size_t)L * FFDIM * EMBED;
        const size_t oF  = (size_t)L * FFDIM;

        // activation split (stream 0), then fork K/V work to side streams
        conv(cur, pah, pal, ROWS * EMBED, s0);
        cudaEventRecord(ev0, s0);
        cudaStreamWaitEvent(st1, ev0, 0);
        cudaStreamWaitEvent(st2, ev0, 0);

        // stream 1: K projection, then W1 conversion (overlaps attn/O-proj)
        conv(Wk + oEE, pwkh, pwkl, EMBED * EMBED, st1);
        gemm_mma_bf16x3<<<gE, 256, GEMM_SMEM, st1>>>(pah, pal, pwkh, pwkl,
                                                     bk + oE, pk, EMBED, EMBED, 0);
        cudaEventRecord(evK, st1);
        conv(W1 + oFE, pw1h, pw1l, FFDIM * EMBED, st1);
        cudaEventRecord(evW1, st1);

        // stream 2: V projection, then W2 conversion
        conv(Wv + oEE, pwvh, pwvl, EMBED * EMBED, st2);
        gemm_mma_bf16x3<<<gE, 256, GEMM_SMEM, st2>>>(pah, pal, pwvh, pwvl,
                                                     bv + oE, pv, EMBED, EMBED, 0);
        cudaEventRecord(evV, st2);
        conv(W2 + oFE, pw2h, pw2l, FFDIM * EMBED, st2);
        cudaEventRecord(evW2, st2);

        // stream 0: Q projection + Wo conversion (overlaps with K/V gemms)
        conv(Wq + oEE, pwh, pwl, EMBED * EMBED, s0);
        gemm_mma_bf16x3<<<gE, 256, GEMM_SMEM, s0>>>(pah, pal, pwh, pwl,
                                                    bq + oE, pq, EMBED, EMBED, 0);
        conv(Wo + oEE, pwh, pwl, EMBED * EMBED, s0);  // safe: after Q gemm on s0

        // join K/V, run attention
        cudaStreamWaitEvent(s0, evK, 0);
        cudaStreamWaitEvent(s0, evV, 0);
        band_attn<<<gA, 256, ATTN_SMEM_BYTES, s0>>>(pq, pk, pv, pattn);

        // O projection + LN1
        conv(pattn, pah, pal, ROWS * EMBED, s0);
        gemm_mma_bf16x3<<<gE, 256, GEMM_SMEM, s0>>>(pah, pal, pwh, pwl,
                                                    bo + oE, pproj, EMBED, EMBED, 0);
        add_ln<<<ROWS, 256, 0, s0>>>(cur, pproj, g1 + oE, be1 + oE, px2);

        // FF1
        conv(px2, pah, pal, ROWS * EMBED, s0);
        cudaStreamWaitEvent(s0, evW1, 0);
        gemm_mma_bf16x3<<<gF, 256, GEMM_SMEM, s0>>>(pah, pal, pw1h, pw1l,
                                                    b1 + oF, pff, EMBED, FFDIM, 1);

        // FF2
        conv(pff, pfh, pfl, ROWS * FFDIM, s0);
        cudaStreamWaitEvent(s0, evW2, 0);
        gemm_mma_bf16x3<<<gE, 256, GEMM_SMEM, s0>>>(pfh, pfl, pw2h, pw2l,
                                                    b2 + oE, pproj, FFDIM, EMBED, 0);

        float* dst = (L == LAYERS - 1) ? out : px;
        add_ln<<<ROWS, 256, 0, s0>>>(px2, pproj, g2 + oE, be2 + oE, dst);
        cur = px;
    }
}

// round 16
// speedup vs baseline: 2.4488x; 1.0300x over previous
#include <cuda_runtime.h>
#include <cuda_bf16.h>
#include <math.h>
#include <stdint.h>

// ---------------- problem constants ----------------
#define EMBED    1024
#define HEADS    16
#define HEAD_DIM 64
#define FFDIM    4096
#define LAYERS   4
#define BATCH    2
#define SEQ      2048
#define ROWS     (BATCH * SEQ)   // 4096
#define BANDW    46              // ceil(sqrt(2048))

// attention tiling
#define QT    64
#define KT    (QT + 2 * BANDW)   // 156
#define PITCH 68                 // padded row pitch (floats) for K/V smem
#define SBW   97                 // band score slots per row

// ---------------- scratch (device globals; no allocation allowed) ----------------
__device__ __align__(256) float g_q[ROWS * EMBED];
__device__ __align__(256) float g_k[ROWS * EMBED];
__device__ __align__(256) float g_v[ROWS * EMBED];
__device__ __align__(256) float g_proj[ROWS * EMBED];
__device__ __align__(256) float g_x[ROWS * EMBED];
__device__ __align__(256) float g_x2[ROWS * EMBED];

// split-precision bf16 operand buffers
__device__ __align__(256) __nv_bfloat16 g_ah[ROWS * EMBED];
__device__ __align__(256) __nv_bfloat16 g_al[ROWS * EMBED];
__device__ __align__(256) __nv_bfloat16 g_fh[ROWS * FFDIM];
__device__ __align__(256) __nv_bfloat16 g_fl[ROWS * FFDIM];
// per-stream weight buffers
__device__ __align__(256) __nv_bfloat16 g_wh[EMBED * EMBED];    // Wq (stream 0)
__device__ __align__(256) __nv_bfloat16 g_wl[EMBED * EMBED];
__device__ __align__(256) __nv_bfloat16 g_wkh[EMBED * EMBED];   // Wk (stream 1)
__device__ __align__(256) __nv_bfloat16 g_wkl[EMBED * EMBED];
__device__ __align__(256) __nv_bfloat16 g_wvh[EMBED * EMBED];   // Wv (stream 2)
__device__ __align__(256) __nv_bfloat16 g_wvl[EMBED * EMBED];
__device__ __align__(256) __nv_bfloat16 g_woh[EMBED * EMBED];   // Wo (stream 2)
__device__ __align__(256) __nv_bfloat16 g_wol[EMBED * EMBED];
__device__ __align__(256) __nv_bfloat16 g_w1h[FFDIM * EMBED];   // W1 (stream 1)
__device__ __align__(256) __nv_bfloat16 g_w1l[FFDIM * EMBED];
__device__ __align__(256) __nv_bfloat16 g_w2h[FFDIM * EMBED];   // W2 (stream 2)
__device__ __align__(256) __nv_bfloat16 g_w2l[FFDIM * EMBED];

// ================= helpers =================
__device__ __forceinline__ uint32_t smem_u32(const void* p) {
    uint32_t a;
    asm("{ .reg .u64 t; cvta.to.shared.u64 t, %1; cvt.u32.u64 %0, t; }"
        : "=r"(a) : "l"(p));
    return a;
}

__device__ __forceinline__ void ldsm4(uint32_t r[4], uint32_t addr) {
    asm volatile("ldmatrix.sync.aligned.m8n8.x4.shared.b16 {%0,%1,%2,%3}, [%4];"
                 : "=r"(r[0]), "=r"(r[1]), "=r"(r[2]), "=r"(r[3]) : "r"(addr));
}

__device__ __forceinline__ void mma16816(float c[4], const uint32_t a[4],
                                         uint32_t b0, uint32_t b1) {
    asm volatile(
        "mma.sync.aligned.m16n8k16.row.col.f32.bf16.bf16.f32 "
        "{%0,%1,%2,%3}, {%4,%5,%6,%7}, {%8,%9}, {%0,%1,%2,%3};"
        : "+f"(c[0]), "+f"(c[1]), "+f"(c[2]), "+f"(c[3])
        : "r"(a[0]), "r"(a[1]), "r"(a[2]), "r"(a[3]), "r"(b0), "r"(b1));
}

#define CP_ASYNC16(dst, src) \
    asm volatile("cp.async.cg.shared.global [%0], [%1], 16;" :: "r"(dst), "l"(src))
#define CP_COMMIT() asm volatile("cp.async.commit_group;" ::: "memory")
#define CP_WAIT1()  asm volatile("cp.async.wait_group 1;" ::: "memory")

// split a pair of fp32 into packed bf16 hi / lo (residual) words
__device__ __forceinline__ void split_pair(float a, float b, uint32_t& h, uint32_t& l) {
    __nv_bfloat16 ha = __float2bfloat16(a);
    __nv_bfloat16 hb = __float2bfloat16(b);
    float ra = a - __bfloat162float(ha);
    float rb = b - __bfloat162float(hb);
    __nv_bfloat162 hh; hh.x = ha; hh.y = hb;
    __nv_bfloat162 ll; ll.x = __float2bfloat16(ra); ll.y = __float2bfloat16(rb);
    h = *(uint32_t*)&hh;
    l = *(uint32_t*)&ll;
}

// ================= split conversion: fp32 -> (bf16 hi, bf16 lo) =================
__global__ __launch_bounds__(256) void convert_split(
    const float* __restrict__ in, __nv_bfloat16* __restrict__ hi,
    __nv_bfloat16* __restrict__ lo, int n)
{
    int i = (blockIdx.x * 256 + threadIdx.x) * 8;
    if (i >= n) return;
    float4 a = *(const float4*)(in + i);
    float4 b = *(const float4*)(in + i + 4);
    float v[8] = {a.x, a.y, a.z, a.w, b.x, b.y, b.z, b.w};
    uint4 hv, lv;
    uint32_t* hp = (uint32_t*)&hv;
    uint32_t* lp = (uint32_t*)&lv;
#pragma unroll
    for (int j = 0; j < 4; j++) split_pair(v[j * 2], v[j * 2 + 1], hp[j], lp[j]);
    *(uint4*)(hi + i) = hv;
    *(uint4*)(lo + i) = lv;
}

// ================= split-precision GEMM via mma.sync (HMMA) =================
// out = (Ah+Al)[M,K] @ (Bh+Bl)[N,K]^T + bias ; fp32 accumulation in registers.
// Writes fp32 C (if non-null) and/or split bf16 Ch/Cl (if non-null).
// CTA = 128x128, 8 warps (2m x 4n), warp tile 64x32, BK = 64, 3-stage cp.async.
#define TILE_B   16384                 // one operand tile: 128 rows x 128B
#define STAGE_B  (4 * TILE_B)          // Ah, Al, Bh, Bl
#define NSTAGE   3
#define GEMM_SMEM (NSTAGE * STAGE_B)   // 196608

// swizzled 16B-chunk offset within one tile: row 0..127, chunk 0..7
__device__ __forceinline__ uint32_t swz(int row, int chunk) {
    return (uint32_t)((row * 8 + (chunk ^ (row & 7))) << 4);
}

__device__ __forceinline__ void load_stage(
    uint32_t sbase,
    const __nv_bfloat16* A0, const __nv_bfloat16* A1,
    const __nv_bfloat16* B0, const __nv_bfloat16* B1,
    int k0, int K, int tid)
{
    const int c  = tid & 7;        // 16B chunk within 128B row
    const int r0 = tid >> 3;       // 0..31
    const __nv_bfloat16* srcs[4] = {A0, A1, B0, B1};
#pragma unroll
    for (int t = 0; t < 4; t++) {
        const uint32_t tb = sbase + t * TILE_B;
        const __nv_bfloat16* sp = srcs[t] + k0 + c * 8;
#pragma unroll
        for (int i = 0; i < 4; i++) {
            int row = r0 + i * 32;
            uint32_t dst = tb + swz(row, c);
            CP_ASYNC16(dst, sp + (size_t)row * K);
        }
    }
}

__global__ __launch_bounds__(256) void gemm_mma_bf16x3(
    const __nv_bfloat16* __restrict__ Ah, const __nv_bfloat16* __restrict__ Al,
    const __nv_bfloat16* __restrict__ Bh, const __nv_bfloat16* __restrict__ Bl,
    const float* __restrict__ bias, float* __restrict__ C,
    __nv_bfloat16* __restrict__ Ch, __nv_bfloat16* __restrict__ Cl,
    int K, int N, int relu)
{
    extern __shared__ __align__(1024) char smem[];
    const uint32_t sb = smem_u32(smem);

    const int tid    = threadIdx.x;
    const int lane   = tid & 31;
    const int wid    = tid >> 5;
    const int warp_m = wid >> 2;     // 0..1
    const int warp_n = wid & 3;      // 0..3
    const int m0 = blockIdx.y * 128;
    const int n0 = blockIdx.x * 128;

    const __nv_bfloat16* A0 = Ah + (size_t)m0 * K;
    const __nv_bfloat16* A1 = Al + (size_t)m0 * K;
    const __nv_bfloat16* B0 = Bh + (size_t)n0 * K;
    const __nv_bfloat16* B1 = Bl + (size_t)n0 * K;

    const int S = K >> 6;

    load_stage(sb + 0 * STAGE_B, A0, A1, B0, B1, 0, K, tid);
    CP_COMMIT();
    load_stage(sb + 1 * STAGE_B, A0, A1, B0, B1, 64, K, tid);
    CP_COMMIT();

    float acc[4][4][4];
#pragma unroll
    for (int a = 0; a < 4; a++)
#pragma unroll
        for (int b = 0; b < 4; b++)
#pragma unroll
            for (int c = 0; c < 4; c++) acc[a][b][c] = 0.f;

    // lane-derived fragment addressing terms
    const int a_row_lo = (lane & 7) + (((lane >> 3) & 1) << 3);
    const int a_cbit   = (lane >> 4) & 1;
    const int b_row_lo = (lane & 7) + (((lane >> 4) & 1) << 3);
    const int b_cbit   = (lane >> 3) & 1;

    for (int kt = 0; kt < S; kt++) {
        CP_WAIT1();
        __syncthreads();
        if (kt + 2 < S) {
            load_stage(sb + ((kt + 2) % NSTAGE) * STAGE_B,
                       A0, A1, B0, B1, (kt + 2) * 64, K, tid);
        }
        CP_COMMIT();

        const uint32_t st = sb + (kt % NSTAGE) * STAGE_B;
        const uint32_t aAh = st;
        const uint32_t aAl = st + TILE_B;
        const uint32_t aBh = st + 2 * TILE_B;
        const uint32_t aBl = st + 3 * TILE_B;

#pragma unroll
        for (int ks = 0; ks < 4; ks++) {
            uint32_t ah[4][4], al[4][4];
#pragma unroll
            for (int mt = 0; mt < 4; mt++) {
                int row   = warp_m * 64 + mt * 16 + a_row_lo;
                int chunk = ks * 2 + a_cbit;
                uint32_t off = swz(row, chunk);
                ldsm4(ah[mt], aAh + off);
                ldsm4(al[mt], aAl + off);
            }
            uint32_t bh[2][4], bl[2][4];
#pragma unroll
            for (int bp = 0; bp < 2; bp++) {
                int row   = warp_n * 32 + bp * 16 + b_row_lo;
                int chunk = ks * 2 + b_cbit;
                uint32_t off = swz(row, chunk);
                ldsm4(bh[bp], aBh + off);
                ldsm4(bl[bp], aBl + off);
            }
#pragma unroll
            for (int mt = 0; mt < 4; mt++) {
#pragma unroll
                for (int nt = 0; nt < 4; nt++) {
                    uint32_t b0h = bh[nt >> 1][(nt & 1) * 2];
                    uint32_t b1h = bh[nt >> 1][(nt & 1) * 2 + 1];
                    uint32_t b0l = bl[nt >> 1][(nt & 1) * 2];
                    uint32_t b1l = bl[nt >> 1][(nt & 1) * 2 + 1];
                    mma16816(acc[mt][nt], ah[mt], b0h, b1h);
                    mma16816(acc[mt][nt], ah[mt], b0l, b1l);
                    mma16816(acc[mt][nt], al[mt], b0h, b1h);
                }
            }
        }
    }

    // epilogue: bias + optional ReLU; fp32 and/or split bf16 stores
    const int rbase = m0 + warp_m * 64 + (lane >> 2);
    const int cbase = n0 + warp_n * 32 + (lane & 3) * 2;
#pragma unroll
    for (int nt = 0; nt < 4; nt++) {
        int col = cbase + nt * 8;
        float bv0 = __ldg(bias + col);
        float bv1 = __ldg(bias + col + 1);
#pragma unroll
        for (int mt = 0; mt < 4; mt++) {
            int r = rbase + mt * 16;
            float c0 = acc[mt][nt][0] + bv0;
            float c1 = acc[mt][nt][1] + bv1;
            float c2 = acc[mt][nt][2] + bv0;
            float c3 = acc[mt][nt][3] + bv1;
            if (relu) {
                c0 = fmaxf(c0, 0.f); c1 = fmaxf(c1, 0.f);
                c2 = fmaxf(c2, 0.f); c3 = fmaxf(c3, 0.f);
            }
            if (C) {
                *(float2*)(C + (size_t)r * N + col)       = make_float2(c0, c1);
                *(float2*)(C + (size_t)(r + 8) * N + col) = make_float2(c2, c3);
            }
            if (Ch) {
                uint32_t h0, l0, h1, l1;
                split_pair(c0, c1, h0, l0);
                split_pair(c2, c3, h1, l1);
                *(uint32_t*)(Ch + (size_t)r * N + col)       = h0;
                *(uint32_t*)(Cl + (size_t)r * N + col)       = l0;
                *(uint32_t*)(Ch + (size_t)(r + 8) * N + col) = h1;
                *(uint32_t*)(Cl + (size_t)(r + 8) * N + col) = l1;
            }
        }
    }
}

// ---------------- banded attention, v3: writes split bf16 output ----------------
#define ATTN_SMEM_FLOATS (2 * KT * PITCH + QT * SBW)
#define ATTN_SMEM_BYTES  (ATTN_SMEM_FLOATS * 4)

__global__ __launch_bounds__(256, 2) void band_attn(
    const float* __restrict__ q, const float* __restrict__ k,
    const float* __restrict__ v,
    __nv_bfloat16* __restrict__ oh, __nv_bfloat16* __restrict__ ol)
{
    extern __shared__ float sm[];
    float* Ks = sm;                       // KT * PITCH
    float* Vs = Ks + KT * PITCH;          // KT * PITCH
    float* Ss = Vs + KT * PITCH;          // QT * SBW

    const int t  = threadIdx.x;           // 256
    const int q0 = blockIdx.x * QT;
    const int h  = blockIdx.y;
    const int b  = blockIdx.z;
    const size_t hoff = (size_t)h * HEAD_DIM;

    const int i  = t >> 2;                // query row 0..63
    const int jl = t & 3;                 // lane-within-row 0..3

    for (int idx = t; idx < KT * 16; idx += 256) {
        int jj = idx >> 4;
        int d4 = (idx & 15) * 4;
        int j  = q0 - BANDW + jj;
        float4 kv = make_float4(0.f, 0.f, 0.f, 0.f);
        float4 vv = make_float4(0.f, 0.f, 0.f, 0.f);
        if (j >= 0 && j < SEQ) {
            size_t base = ((size_t)(b * SEQ + j) * EMBED) + hoff + d4;
            kv = *(const float4*)(k + base);
            vv = *(const float4*)(v + base);
        }
        Ks[jj * PITCH + d4 + 0] = kv.x;
        Ks[jj * PITCH + d4 + 1] = kv.y;
        Ks[jj * PITCH + d4 + 2] = kv.z;
        Ks[jj * PITCH + d4 + 3] = kv.w;
        Vs[jj * PITCH + d4 + 0] = vv.x;
        Vs[jj * PITCH + d4 + 1] = vv.y;
        Vs[jj * PITCH + d4 + 2] = vv.z;
        Vs[jj * PITCH + d4 + 3] = vv.w;
    }

    float qreg[64];
    {
        const float* qrow = q + ((size_t)(b * SEQ + q0 + i) * EMBED) + hoff;
#pragma unroll
        for (int d4 = 0; d4 < 16; d4++) {
            float4 val = __ldg((const float4*)qrow + d4);
            qreg[d4 * 4 + 0] = val.x;
            qreg[d4 * 4 + 1] = val.y;
            qreg[d4 * 4 + 2] = val.z;
            qreg[d4 * 4 + 3] = val.w;
        }
    }
    __syncthreads();

    const float scale = 0.125f;  // 1/sqrt(64)
    for (int s = jl; s <= 92; s += 4) {
        int jj = i + s;
        int j  = q0 - BANDW + jj;
        float sc = -1e9f;
        if (j >= 0 && j < SEQ) {
            const float* kp = Ks + jj * PITCH;
            float a0 = 0.f, a1 = 0.f, a2 = 0.f, a3 = 0.f;
#pragma unroll
            for (int d4 = 0; d4 < 16; d4++) {
                float4 kk = *(const float4*)(kp + d4 * 4);
                a0 += qreg[d4 * 4 + 0] * kk.x;
                a1 += qreg[d4 * 4 + 1] * kk.y;
                a2 += qreg[d4 * 4 + 2] * kk.z;
                a3 += qreg[d4 * 4 + 3] * kk.w;
            }
            sc = (a0 + a1 + a2 + a3) * scale;
        }
        Ss[i * SBW + s] = sc;
    }
    __syncthreads();

    {
        float* srow = Ss + i * SBW;
        const int lo = jl * 24;
        const int hi = (jl == 3) ? 93 : lo + 24;
        float mx = -1e30f;
        for (int s = lo; s < hi; s++) mx = fmaxf(mx, srow[s]);
        mx = fmaxf(mx, __shfl_xor_sync(0xffffffffu, mx, 1));
        mx = fmaxf(mx, __shfl_xor_sync(0xffffffffu, mx, 2));
        float sum = 0.f;
        for (int s = lo; s < hi; s++) {
            float e = expf(srow[s] - mx);
            srow[s] = e;
            sum += e;
        }
        sum += __shfl_xor_sync(0xffffffffu, sum, 1);
        sum += __shfl_xor_sync(0xffffffffu, sum, 2);
        float inv = 1.f / sum;
        for (int s = lo; s < hi; s++) srow[s] *= inv;
    }
    __syncthreads();

    const int c = jl;
    float acc[16];
#pragma unroll
    for (int kk = 0; kk < 16; kk++) acc[kk] = 0.f;
    const float* prow = Ss + i * SBW;
    for (int s = 0; s <= 92; s++) {
        int jj = i + s;
        float p = prow[s];
        const float* vp = Vs + jj * PITCH + c * 16;
#pragma unroll
        for (int k4 = 0; k4 < 4; k4++) {
            int ch = (k4 + (c & 2)) & 3;
            float4 vv = *(const float4*)(vp + ch * 4);
            acc[ch * 4 + 0] += p * vv.x;
            acc[ch * 4 + 1] += p * vv.y;
            acc[ch * 4 + 2] += p * vv.z;
            acc[ch * 4 + 3] += p * vv.w;
        }
    }
    // split output: 16 bf16 hi + 16 bf16 lo = 2x 16B stores each
    uint4 hv0, hv1, lv0, lv1;
    uint32_t* hp0 = (uint32_t*)&hv0; uint32_t* hp1 = (uint32_t*)&hv1;
    uint32_t* lp0 = (uint32_t*)&lv0; uint32_t* lp1 = (uint32_t*)&lv1;
#pragma unroll
    for (int p2 = 0; p2 < 4; p2++)
        split_pair(acc[p2 * 2], acc[p2 * 2 + 1], hp0[p2], lp0[p2]);
#pragma unroll
    for (int p2 = 0; p2 < 4; p2++)
        split_pair(acc[8 + p2 * 2], acc[8 + p2 * 2 + 1], hp1[p2], lp1[p2]);
    size_t obase = ((size_t)(b * SEQ + q0 + i) * EMBED) + hoff + c * 16;
    *(uint4*)(oh + obase)     = hv0;
    *(uint4*)(oh + obase + 8) = hv1;
    *(uint4*)(ol + obase)     = lv0;
    *(uint4*)(ol + obase + 8) = lv1;
}

// ---------------- fused residual add + LayerNorm (+ optional split out) ----------------
__global__ __launch_bounds__(256) void add_ln(
    const float* __restrict__ r, const float* __restrict__ p,
    const float* __restrict__ g, const float* __restrict__ be,
    float* __restrict__ y,
    __nv_bfloat16* __restrict__ yh, __nv_bfloat16* __restrict__ yl)
{
    const int row = blockIdx.x;
    const int t = threadIdx.x;
    const size_t base = (size_t)row * EMBED + t * 4;
    float4 rv = *(const float4*)(r + base);
    float4 pv = *(const float4*)(p + base);
    float z0 = rv.x + pv.x, z1 = rv.y + pv.y, z2 = rv.z + pv.z, z3 = rv.w + pv.w;
    float s  = z0 + z1 + z2 + z3;
    float sq = z0 * z0 + z1 * z1 + z2 * z2 + z3 * z3;
#pragma unroll
    for (int off = 16; off > 0; off >>= 1) {
        s  += __shfl_xor_sync(0xffffffffu, s, off);
        sq += __shfl_xor_sync(0xffffffffu, sq, off);
    }
    __shared__ float ws[8], wsq[8];
    __shared__ float mu_s, rstd_s;
    const int warp = t >> 5, lane = t & 31;
    if (lane == 0) { ws[warp] = s; wsq[warp] = sq; }
    __syncthreads();
    if (t == 0) {
        float ts = 0.f, tsq = 0.f;
#pragma unroll
        for (int wdx = 0; wdx < 8; wdx++) { ts += ws[wdx]; tsq += wsq[wdx]; }
        float mu = ts * (1.f / EMBED);
        float var = tsq * (1.f / EMBED) - mu * mu;
        mu_s = mu;
        rstd_s = rsqrtf(var + 1e-5f);
    }
    __syncthreads();
    float mu = mu_s, rstd = rstd_s;
    float4 gv = *(const float4*)(g + t * 4);
    float4 bv = *(const float4*)(be + t * 4);
    float o0 = (z0 - mu) * rstd * gv.x + bv.x;
    float o1 = (z1 - mu) * rstd * gv.y + bv.y;
    float o2 = (z2 - mu) * rstd * gv.z + bv.z;
    float o3 = (z3 - mu) * rstd * gv.w + bv.w;
    *(float4*)(y + base) = make_float4(o0, o1, o2, o3);
    if (yh) {
        uint2 hv, lv;
        split_pair(o0, o1, hv.x, lv.x);
        split_pair(o2, o3, hv.y, lv.y);
        *(uint2*)(yh + base) = hv;
        *(uint2*)(yl + base) = lv;
    }
}

// ---------------- launch ----------------
static inline void conv(const float* in, __nv_bfloat16* hi, __nv_bfloat16* lo,
                        int n, cudaStream_t st) {
    convert_split<<<n / 2048, 256, 0, st>>>(in, hi, lo, n);
}

extern "C" void kernel_launch(void* const* d_in, const int* in_sizes, int n_in,
                              void* d_out, int out_size)
{
    static bool inited = false;
    static float *pq, *pk, *pv, *pproj, *px, *px2;
    static __nv_bfloat16 *pah, *pal, *pfh, *pfl;
    static __nv_bfloat16 *pwh, *pwl, *pwkh, *pwkl, *pwvh, *pwvl, *pwoh, *pwol;
    static __nv_bfloat16 *pw1h, *pw1l, *pw2h, *pw2l;
    static cudaStream_t st1, st2;
    static cudaEvent_t ev0, evK, evV, evWo, evW1, evW2;
    if (!inited) {
        cudaGetSymbolAddress((void**)&pq,    g_q);
        cudaGetSymbolAddress((void**)&pk,    g_k);
        cudaGetSymbolAddress((void**)&pv,    g_v);
        cudaGetSymbolAddress((void**)&pproj, g_proj);
        cudaGetSymbolAddress((void**)&px,    g_x);
        cudaGetSymbolAddress((void**)&px2,   g_x2);
        cudaGetSymbolAddress((void**)&pah,   g_ah);
        cudaGetSymbolAddress((void**)&pal,   g_al);
        cudaGetSymbolAddress((void**)&pfh,   g_fh);
        cudaGetSymbolAddress((void**)&pfl,   g_fl);
        cudaGetSymbolAddress((void**)&pwh,   g_wh);
        cudaGetSymbolAddress((void**)&pwl,   g_wl);
        cudaGetSymbolAddress((void**)&pwkh,  g_wkh);
        cudaGetSymbolAddress((void**)&pwkl,  g_wkl);
        cudaGetSymbolAddress((void**)&pwvh,  g_wvh);
        cudaGetSymbolAddress((void**)&pwvl,  g_wvl);
        cudaGetSymbolAddress((void**)&pwoh,  g_woh);
        cudaGetSymbolAddress((void**)&pwol,  g_wol);
        cudaGetSymbolAddress((void**)&pw1h,  g_w1h);
        cudaGetSymbolAddress((void**)&pw1l,  g_w1l);
        cudaGetSymbolAddress((void**)&pw2h,  g_w2h);
        cudaGetSymbolAddress((void**)&pw2l,  g_w2l);
        cudaFuncSetAttribute(band_attn, cudaFuncAttributeMaxDynamicSharedMemorySize,
                             ATTN_SMEM_BYTES);
        cudaFuncSetAttribute(gemm_mma_bf16x3, cudaFuncAttributeMaxDynamicSharedMemorySize,
                             GEMM_SMEM);
        cudaStreamCreateWithFlags(&st1, cudaStreamNonBlocking);
        cudaStreamCreateWithFlags(&st2, cudaStreamNonBlocking);
        cudaEventCreateWithFlags(&ev0,  cudaEventDisableTiming);
        cudaEventCreateWithFlags(&evK,  cudaEventDisableTiming);
        cudaEventCreateWithFlags(&evV,  cudaEventDisableTiming);
        cudaEventCreateWithFlags(&evWo, cudaEventDisableTiming);
        cudaEventCreateWithFlags(&evW1, cudaEventDisableTiming);
        cudaEventCreateWithFlags(&evW2, cudaEventDisableTiming);
        inited = true;
    }

    const float* x   = (const float*)d_in[0];
    const float* Wq  = (const float*)d_in[1];
    const float* bq  = (const float*)d_in[2];
    const float* Wk  = (const float*)d_in[3];
    const float* bk  = (const float*)d_in[4];
    const float* Wv  = (const float*)d_in[5];
    const float* bv  = (const float*)d_in[6];
    const float* Wo  = (const float*)d_in[7];
    const float* bo  = (const float*)d_in[8];
    const float* W1  = (const float*)d_in[9];
    const float* b1  = (const float*)d_in[10];
    const float* W2  = (const float*)d_in[11];
    const float* b2  = (const float*)d_in[12];
    const float* g1  = (const float*)d_in[13];
    const float* be1 = (const float*)d_in[14];
    const float* g2  = (const float*)d_in[15];
    const float* be2 = (const float*)d_in[16];
    float* out = (float*)d_out;

    const dim3 gE(EMBED / 128, ROWS / 128);   // (8, 32)
    const dim3 gF(FFDIM / 128, ROWS / 128);   // (32, 32)
    const dim3 gA(SEQ / QT, HEADS, BATCH);    // (32, 16, 2)
    cudaStream_t s0 = 0;

    const float* cur = x;
    for (int L = 0; L < LAYERS; L++) {
        const size_t oEE = (size_t)L * EMBED * EMBED;
        const size_t oE  = (size_t)L * EMBED;
        const size_t oFE = (size_t)L * FFDIM * EMBED;
        const size_t oF  = (size_t)L * FFDIM;

        // layer 0: build initial activation split from input x
        if (L == 0) conv(cur, pah, pal, ROWS * EMBED, s0);
        // fork: side streams get activation split + previous-layer drain point
        cudaEventRecord(ev0, s0);
        cudaStreamWaitEvent(st1, ev0, 0);
        cudaStreamWaitEvent(st2, ev0, 0);

        // stream 1: K projection, then W1 conversion
        conv(Wk + oEE, pwkh, pwkl, EMBED * EMBED, st1);
        gemm_mma_bf16x3<<<gE, 256, GEMM_SMEM, st1>>>(pah, pal, pwkh, pwkl,
            bk + oE, pk, (__nv_bfloat16*)0, (__nv_bfloat16*)0, EMBED, EMBED, 0);
        cudaEventRecord(evK, st1);
        conv(W1 + oFE, pw1h, pw1l, FFDIM * EMBED, st1);
        cudaEventRecord(evW1, st1);

        // stream 2: V projection, then Wo + W2 conversions
        conv(Wv + oEE, pwvh, pwvl, EMBED * EMBED, st2);
        gemm_mma_bf16x3<<<gE, 256, GEMM_SMEM, st2>>>(pah, pal, pwvh, pwvl,
            bv + oE, pv, (__nv_bfloat16*)0, (__nv_bfloat16*)0, EMBED, EMBED, 0);
        cudaEventRecord(evV, st2);
        conv(Wo + oEE, pwoh, pwol, EMBED * EMBED, st2);
        cudaEventRecord(evWo, st2);
        conv(W2 + oFE, pw2h, pw2l, FFDIM * EMBED, st2);
        cudaEventRecord(evW2, st2);

        // stream 0: Q projection
        conv(Wq + oEE, pwh, pwl, EMBED * EMBED, s0);
        gemm_mma_bf16x3<<<gE, 256, GEMM_SMEM, s0>>>(pah, pal, pwh, pwl,
            bq + oE, pq, (__nv_bfloat16*)0, (__nv_bfloat16*)0, EMBED, EMBED, 0);

        // attention: writes split output into pah/pal
        cudaStreamWaitEvent(s0, evK, 0);
        cudaStreamWaitEvent(s0, evV, 0);
        band_attn<<<gA, 256, ATTN_SMEM_BYTES, s0>>>(pq, pk, pv, pah, pal);

        // O projection (split input) + LN1 (emits FF1's split input)
        cudaStreamWaitEvent(s0, evWo, 0);
        gemm_mma_bf16x3<<<gE, 256, GEMM_SMEM, s0>>>(pah, pal, pwoh, pwol,
            bo + oE, pproj, (__nv_bfloat16*)0, (__nv_bfloat16*)0, EMBED, EMBED, 0);
        add_ln<<<ROWS, 256, 0, s0>>>(cur, pproj, g1 + oE, be1 + oE, px2, pah, pal);

        // FF1: split output only (ReLU applied before split)
        cudaStreamWaitEvent(s0, evW1, 0);
        gemm_mma_bf16x3<<<gF, 256, GEMM_SMEM, s0>>>(pah, pal, pw1h, pw1l,
            b1 + oF, (float*)0, pfh, pfl, EMBED, FFDIM, 1);

        // FF2: fp32 output
        cudaStreamWaitEvent(s0, evW2, 0);
        gemm_mma_bf16x3<<<gE, 256, GEMM_SMEM, s0>>>(pfh, pfl, pw2h, pw2l,
            b2 + oE, pproj, (__nv_bfloat16*)0, (__nv_bfloat16*)0, FFDIM, EMBED, 0);

        // LN2: fp32 out + next layer's activation split
        float* dst = (L == LAYERS - 1) ? out : px;
        __nv_bfloat16* nh = (L == LAYERS - 1) ? (__nv_bfloat16*)0 : pah;
        __nv_bfloat16* nl = (L == LAYERS - 1) ? (__nv_bfloat16*)0 : pal;
        add_ln<<<ROWS, 256, 0, s0>>>(px2, pproj, g2 + oE, be2 + oE, dst, nh, nl);
        cur = px;
    }
}